// round 2
// baseline (speedup 1.0000x reference)
#include <cuda_runtime.h>
#include <cuda_bf16.h>
#include <math.h>

#define CDIM 128
#define KDIM 128
#define MT 128
#define CCHUNK 32
#define MS 132            // Xs row stride (words): float4-aligned
#define NMAX (1 << 20)

// Replay-safe device scratch (no allocations allowed)
__device__ double g_acc;
__device__ int    g_cnt;
__device__ int    g_idx[NMAX];

__global__ void k_zero() { g_acc = 0.0; g_cnt = 0; }

// Pass 1: compact unlabeled row indices; compute nll for labeled rows.
__global__ void k_labeled(const float* __restrict__ x, const int* __restrict__ labels,
                          const int* __restrict__ kp, int N)
{
    int k = kp ? *kp : 128;
    int lane = threadIdx.x & 31;
    int wpb  = blockDim.x >> 5;
    int gw   = blockIdx.x * wpb + (threadIdx.x >> 5);
    int nw   = gridDim.x * wpb;
    double wsum = 0.0;

    for (int base = gw * 32; base < N; base += nw * 32) {
        int row = base + lane;
        bool valid = row < N;
        int lab = valid ? labels[row] : 0;
        bool unl = valid && (lab > k - 1);

        // warp-aggregated compaction of unlabeled rows
        unsigned um = __ballot_sync(0xffffffffu, unl);
        int c = __popc(um);
        int pos = 0;
        if (lane == 0 && c) pos = atomicAdd(&g_cnt, c);
        pos = __shfl_sync(0xffffffffu, pos, 0);
        if (unl) g_idx[pos + __popc(um & ((1u << lane) - 1))] = row;

        // labeled rows: warp-cooperative logsumexp + nll
        unsigned lm = __ballot_sync(0xffffffffu, valid && !unl);
        while (lm) {
            int l = __ffs(lm) - 1; lm &= lm - 1;
            int r = base + l;
            int labr = __shfl_sync(0xffffffffu, lab, l);
            const float* xr = x + (size_t)r * CDIM;
            float v0 = xr[lane], v1 = xr[lane + 32], v2 = xr[lane + 64], v3 = xr[lane + 96];
            float mx = fmaxf(fmaxf(v0, v1), fmaxf(v2, v3));
            #pragma unroll
            for (int o = 16; o; o >>= 1) mx = fmaxf(mx, __shfl_xor_sync(0xffffffffu, mx, o));
            float s = __expf(v0 - mx) + __expf(v1 - mx) + __expf(v2 - mx) + __expf(v3 - mx);
            #pragma unroll
            for (int o = 16; o; o >>= 1) s += __shfl_xor_sync(0xffffffffu, s, o);
            int slot = labr >> 5;
            float cand = (slot == 0) ? v0 : (slot == 1) ? v1 : (slot == 2) ? v2 : v3;
            float xl = __shfl_sync(0xffffffffu, cand, labr & 31);
            if (lane == 0) wsum += (double)((mx + __logf(s)) - xl);
        }
    }
    if (lane == 0 && wsum != 0.0) atomicAdd(&g_acc, wsum);
}

// Pass 2: fused GEMM (unlabeled rows only) -> argmax -> logsumexp -> nll.
// score_j = x.p_j - 0.5*||p_j||^2 ; argmax == argmin distance (ties -> lowest j).
// Static smem (<48KB): proto tile is chunked and restaged from L2 each K-chunk.
__global__ void __launch_bounds__(256, 2)
k_gemm(const float* __restrict__ x, const float* __restrict__ protos)
{
    __shared__ float Pt[CCHUNK * KDIM];   // [c within chunk][j]   16 KB
    __shared__ float Xs[CCHUNK * MS];     // [c within chunk][m]   16.9 KB
    __shared__ float qv[KDIM];            // 0.5*||p_j||^2
    __shared__ int   ridx[MT];
    __shared__ int   jb[MT];

    int cnt = g_cnt;
    int tile0 = blockIdx.x * MT;
    if (tile0 >= cnt) return;
    int t = threadIdx.x;

    if (t < MT) {
        int gi = tile0 + t;
        ridx[t] = g_idx[gi < cnt ? gi : cnt - 1];
    }
    if (t < KDIM) {                       // q_j = 0.5*||p_j||^2 (protos L2-hot)
        const float* pr = protos + t * CDIM;
        float s = 0.f;
        #pragma unroll 8
        for (int c = 0; c < CDIM; c++) { float v = pr[c]; s = fmaf(v, v, s); }
        qv[t] = 0.5f * s;
    }

    float acc[8][8];
    #pragma unroll
    for (int i = 0; i < 8; i++)
        #pragma unroll
        for (int j = 0; j < 8; j++) acc[i][j] = 0.f;

    int tx = t & 15, ty = t >> 4;

    for (int c0 = 0; c0 < CDIM; c0 += CCHUNK) {
        __syncthreads();
        // stage proto chunk transposed: [c][j]; lanes vary j -> conflict-free STS
        #pragma unroll
        for (int it = 0; it < 4; it++) {
            int idx = t + it * 256;                   // 0..1023 float4s
            int j  = (idx & 31) + ((idx >> 8) << 5);  // lane-varying j
            int c4 = (idx >> 5) & 7;                  // 8 float4s per 32-c chunk
            float4 pv = *(const float4*)(protos + j * CDIM + c0 + c4 * 4);
            Pt[(c4 * 4 + 0) * KDIM + j] = pv.x;
            Pt[(c4 * 4 + 1) * KDIM + j] = pv.y;
            Pt[(c4 * 4 + 2) * KDIM + j] = pv.z;
            Pt[(c4 * 4 + 3) * KDIM + j] = pv.w;
        }
        // stage X chunk transposed: [c][m]
        #pragma unroll
        for (int it = 0; it < 4; it++) {
            int idx = t + it * 256;                   // 0..1023
            int m = idx >> 3;
            int c4 = idx & 7;
            const float* src = x + (size_t)ridx[m] * CDIM + c0 + c4 * 4;
            float4 v = *(const float4*)src;           // 128B coalesced per 8 lanes
            Xs[(c4 * 4 + 0) * MS + m] = v.x;
            Xs[(c4 * 4 + 1) * MS + m] = v.y;
            Xs[(c4 * 4 + 2) * MS + m] = v.z;
            Xs[(c4 * 4 + 3) * MS + m] = v.w;
        }
        __syncthreads();
        #pragma unroll 4
        for (int cc = 0; cc < CCHUNK; cc++) {
            float4 a0 = *(const float4*)&Xs[cc * MS + ty * 8];
            float4 a1 = *(const float4*)&Xs[cc * MS + ty * 8 + 4];
            float4 b0 = *(const float4*)&Pt[cc * KDIM + tx * 8];
            float4 b1 = *(const float4*)&Pt[cc * KDIM + tx * 8 + 4];
            float av[8] = {a0.x, a0.y, a0.z, a0.w, a1.x, a1.y, a1.z, a1.w};
            float bv[8] = {b0.x, b0.y, b0.z, b0.w, b1.x, b1.y, b1.z, b1.w};
            #pragma unroll
            for (int i = 0; i < 8; i++)
                #pragma unroll
                for (int j = 0; j < 8; j++)
                    acc[i][j] = fmaf(av[i], bv[j], acc[i][j]);
        }
    }

    // per-row argmax: thread-local best-of-8, then width-16 shfl reduce over tx.
    // Combine keeps lowest j on exact ties.
    #pragma unroll
    for (int r = 0; r < 8; r++) {
        float bvv = -INFINITY; int bj = tx * 8;
        #pragma unroll
        for (int n = 0; n < 8; n++) {
            float s = acc[r][n] - qv[tx * 8 + n];
            if (s > bvv) { bvv = s; bj = tx * 8 + n; }
        }
        #pragma unroll
        for (int o = 8; o; o >>= 1) {
            float v2 = __shfl_xor_sync(0xffffffffu, bvv, o, 16);
            int   j2 = __shfl_xor_sync(0xffffffffu, bj,  o, 16);
            if (v2 > bvv || (v2 == bvv && j2 < bj)) { bvv = v2; bj = j2; }
        }
        if (tx == 0) jb[ty * 8 + r] = bj;
    }
    __syncthreads();

    // warp-per-row logsumexp + nll (pseudo-label = jb[row])
    int lane = t & 31, w = t >> 5;
    double lsum = 0.0;
    for (int rr = w; rr < MT; rr += 8) {
        if (tile0 + rr >= cnt) break;                 // uniform within warp
        int row = ridx[rr];
        int jbest = jb[rr];
        const float* xr = x + (size_t)row * CDIM;
        float v0 = xr[lane], v1 = xr[lane + 32], v2 = xr[lane + 64], v3 = xr[lane + 96];
        float mx = fmaxf(fmaxf(v0, v1), fmaxf(v2, v3));
        #pragma unroll
        for (int o = 16; o; o >>= 1) mx = fmaxf(mx, __shfl_xor_sync(0xffffffffu, mx, o));
        float s = __expf(v0 - mx) + __expf(v1 - mx) + __expf(v2 - mx) + __expf(v3 - mx);
        #pragma unroll
        for (int o = 16; o; o >>= 1) s += __shfl_xor_sync(0xffffffffu, s, o);
        int slot = jbest >> 5;
        float cand = (slot == 0) ? v0 : (slot == 1) ? v1 : (slot == 2) ? v2 : v3;
        float xl = __shfl_sync(0xffffffffu, cand, jbest & 31);
        if (lane == 0) lsum += (double)((mx + __logf(s)) - xl);
    }
    if (lane == 0 && lsum != 0.0) atomicAdd(&g_acc, lsum);
}

__global__ void k_final(float* out, int N) { out[0] = (float)(g_acc / (double)N); }

extern "C" void kernel_launch(void* const* d_in, const int* in_sizes, int n_in,
                              void* d_out, int out_size)
{
    const float* x      = (const float*)d_in[0];
    const int*   labels = (const int*)d_in[1];
    const float* protos = (const float*)d_in[2];
    const int*   kp     = (n_in > 3) ? (const int*)d_in[3] : nullptr;
    int N = in_sizes[0] / CDIM;

    k_zero<<<1, 1>>>();
    k_labeled<<<592, 256>>>(x, labels, kp, N);
    int nb = (N + MT - 1) / MT;                 // worst case; excess blocks exit on g_cnt
    k_gemm<<<nb, 256>>>(x, protos);
    k_final<<<1, 1>>>((float*)d_out, N);
}

// round 4
// speedup vs baseline: 2.1117x; 2.1117x over previous
#include <cuda_runtime.h>
#include <cuda_bf16.h>
#include <math.h>
#include <stdint.h>

#define CDIM 128
#define KDIM 128
#define MT 128
#define XS 72              // smem row stride in bf16 (64 data + 8 pad)
#define NMAX (1 << 20)

// ---------------- replay-safe device scratch ----------------
__device__ double g_acc;
__device__ int    g_cnt;
__device__ int    g_idx[NMAX];
__device__ float  g_qv[KDIM];
__device__ unsigned char g_pb[2 * KDIM * 64 * 2];  // protos bf16, [chunk][j][64]

// Prep: reset accumulators, 0.5*||p||^2, protos -> bf16 chunked tiles.
__global__ void k_prep(const float* __restrict__ protos)
{
    int t = threadIdx.x;
    if (t == 0) { g_acc = 0.0; g_cnt = 0; }
    if (t < KDIM) {
        const float* pr = protos + t * CDIM;
        float s = 0.f;
        #pragma unroll 8
        for (int c = 0; c < CDIM; c++) { float v = pr[c]; s = fmaf(v, v, s); }
        g_qv[t] = 0.5f * s;
    }
    // 2 chunks x 128 j x 64 c  = 16384 bf16
    for (int idx = t; idx < 2 * KDIM * 64; idx += blockDim.x) {
        int ch = idx >> 13;
        int j  = (idx >> 6) & 127;
        int kk = idx & 63;
        float v = protos[j * CDIM + ch * 64 + kk];
        ((__nv_bfloat16*)g_pb)[ch * KDIM * 64 + j * 64 + kk] = __float2bfloat16(v);
    }
}

// Pass 1: compact unlabeled rows; nll for labeled rows.
__global__ void k_labeled(const float* __restrict__ x, const int* __restrict__ labels,
                          const int* __restrict__ kp, int N)
{
    int k = kp ? *kp : 128;
    int lane = threadIdx.x & 31;
    int wpb  = blockDim.x >> 5;
    int gw   = blockIdx.x * wpb + (threadIdx.x >> 5);
    int nw   = gridDim.x * wpb;
    double wsum = 0.0;

    for (int base = gw * 32; base < N; base += nw * 32) {
        int row = base + lane;
        bool valid = row < N;
        int lab = valid ? labels[row] : 0;
        bool unl = valid && (lab > k - 1);

        unsigned um = __ballot_sync(0xffffffffu, unl);
        int c = __popc(um);
        int pos = 0;
        if (lane == 0 && c) pos = atomicAdd(&g_cnt, c);
        pos = __shfl_sync(0xffffffffu, pos, 0);
        if (unl) g_idx[pos + __popc(um & ((1u << lane) - 1))] = row;

        unsigned lm = __ballot_sync(0xffffffffu, valid && !unl);
        while (lm) {
            int l = __ffs(lm) - 1; lm &= lm - 1;
            int r = base + l;
            int labr = __shfl_sync(0xffffffffu, lab, l);
            const float* xr = x + (size_t)r * CDIM;
            float v0 = xr[lane], v1 = xr[lane + 32], v2 = xr[lane + 64], v3 = xr[lane + 96];
            float mx = fmaxf(fmaxf(v0, v1), fmaxf(v2, v3));
            #pragma unroll
            for (int o = 16; o; o >>= 1) mx = fmaxf(mx, __shfl_xor_sync(0xffffffffu, mx, o));
            float s = __expf(v0 - mx) + __expf(v1 - mx) + __expf(v2 - mx) + __expf(v3 - mx);
            #pragma unroll
            for (int o = 16; o; o >>= 1) s += __shfl_xor_sync(0xffffffffu, s, o);
            int slot = labr >> 5;
            float cand = (slot == 0) ? v0 : (slot == 1) ? v1 : (slot == 2) ? v2 : v3;
            float xl = __shfl_sync(0xffffffffu, cand, labr & 31);
            if (lane == 0) wsum += (double)((mx + __logf(s)) - xl);
        }
    }
    if (lane == 0 && wsum != 0.0) atomicAdd(&g_acc, wsum);
}

__device__ __forceinline__ void mma16816(float* c4, uint32_t a0, uint32_t a1,
                                         uint32_t a2, uint32_t a3,
                                         uint32_t b0, uint32_t b1) {
    asm volatile("mma.sync.aligned.m16n8k16.row.col.f32.bf16.bf16.f32 "
                 "{%0,%1,%2,%3}, {%4,%5,%6,%7}, {%8,%9}, {%0,%1,%2,%3};"
                 : "+f"(c4[0]), "+f"(c4[1]), "+f"(c4[2]), "+f"(c4[3])
                 : "r"(a0), "r"(a1), "r"(a2), "r"(a3), "r"(b0), "r"(b1));
}

// Pass 2: HMMA bf16 GEMM (unlabeled rows) -> argmax -> fp32 logsumexp -> nll.
__global__ void __launch_bounds__(256)
k_gemm(const float* __restrict__ x)
{
    __shared__ __nv_bfloat16 Xsm[MT * XS];    // [row][c-chunk], 18.4 KB
    __shared__ __nv_bfloat16 Psm[KDIM * XS];  // [j][c-chunk],   18.4 KB
    __shared__ float qs[KDIM];
    __shared__ int   ridx[MT];
    __shared__ int   jb[MT];

    int cnt = g_cnt;
    int tile0 = blockIdx.x * MT;
    if (tile0 >= cnt) return;
    int t = threadIdx.x, wid = t >> 5, lane = t & 31;
    int g = lane >> 2, q = lane & 3;
    int rbase = wid * 16;

    if (t < MT) {
        int gi = tile0 + t;
        ridx[t] = g_idx[gi < cnt ? gi : cnt - 1];
        qs[t]   = g_qv[t];
    }
    __syncthreads();

    float acc[16][4];
    #pragma unroll
    for (int j = 0; j < 16; j++)
        #pragma unroll
        for (int n = 0; n < 4; n++) acc[j][n] = 0.f;

    for (int ch = 0; ch < 2; ch++) {
        if (ch) __syncthreads();
        // stage X chunk: 128 rows x 64 c, fp32 -> bf16
        #pragma unroll
        for (int it = 0; it < 8; it++) {
            int idx = t + it * 256;               // 0..2047 float4s
            int row = idx >> 4, c4 = idx & 15;
            float4 v = *(const float4*)(x + (size_t)ridx[row] * CDIM + ch * 64 + c4 * 4);
            __nv_bfloat162 h0 = __floats2bfloat162_rn(v.x, v.y);
            __nv_bfloat162 h1 = __floats2bfloat162_rn(v.z, v.w);
            uint2 pk; pk.x = *(uint32_t*)&h0; pk.y = *(uint32_t*)&h1;
            *(uint2*)&Xsm[row * XS + c4 * 4] = pk;
        }
        // stage P chunk: copy preconverted bf16 (tight [j][64] -> padded [j][XS])
        #pragma unroll
        for (int it = 0; it < 4; it++) {
            int idx = t + it * 256;               // 0..1023 uint4s (8 bf16 each)
            int j = idx >> 3, c8 = idx & 7;
            *(uint4*)&Psm[j * XS + c8 * 8] =
                *(const uint4*)((const __nv_bfloat16*)g_pb + ch * KDIM * 64 + j * 64 + c8 * 8);
        }
        __syncthreads();

        #pragma unroll
        for (int kk = 0; kk < 4; kk++) {
            const __nv_bfloat16* Xw = &Xsm[(rbase + g) * XS + kk * 16 + q * 2];
            uint32_t a0 = *(const uint32_t*)&Xw[0];
            uint32_t a1 = *(const uint32_t*)&Xw[8 * XS];
            uint32_t a2 = *(const uint32_t*)&Xw[8];
            uint32_t a3 = *(const uint32_t*)&Xw[8 * XS + 8];
            #pragma unroll
            for (int j0 = 0; j0 < 16; j0++) {
                const __nv_bfloat16* Pw = &Psm[(j0 * 8 + g) * XS + kk * 16 + q * 2];
                uint32_t b0 = *(const uint32_t*)&Pw[0];
                uint32_t b1 = *(const uint32_t*)&Pw[8];
                mma16816(acc[j0], a0, a1, a2, a3, b0, b1);
            }
        }
    }

    // argmax: thread covers rows {rbase+g, rbase+g+8}, cols {j0*8+2q, +1}
    float bv0 = -3.0e38f, bv1 = -3.0e38f;
    int bj0 = 0, bj1 = 0;
    #pragma unroll
    for (int j0 = 0; j0 < 16; j0++) {
        int c0 = j0 * 8 + q * 2;
        float q0 = qs[c0], q1 = qs[c0 + 1];
        float s;
        s = acc[j0][0] - q0; if (s > bv0) { bv0 = s; bj0 = c0; }
        s = acc[j0][1] - q1; if (s > bv0) { bv0 = s; bj0 = c0 + 1; }
        s = acc[j0][2] - q0; if (s > bv1) { bv1 = s; bj1 = c0; }
        s = acc[j0][3] - q1; if (s > bv1) { bv1 = s; bj1 = c0 + 1; }
    }
    #pragma unroll
    for (int o = 1; o < 4; o <<= 1) {   // reduce across q group (width-4 segments)
        float v2 = __shfl_xor_sync(0xffffffffu, bv0, o, 4);
        int   j2 = __shfl_xor_sync(0xffffffffu, bj0, o, 4);
        if (v2 > bv0 || (v2 == bv0 && j2 < bj0)) { bv0 = v2; bj0 = j2; }
        v2 = __shfl_xor_sync(0xffffffffu, bv1, o, 4);
        j2 = __shfl_xor_sync(0xffffffffu, bj1, o, 4);
        if (v2 > bv1 || (v2 == bv1 && j2 < bj1)) { bv1 = v2; bj1 = j2; }
    }
    if (q == 0) { jb[rbase + g] = bj0; jb[rbase + g + 8] = bj1; }
    __syncthreads();

    // warp-per-row fp32 logsumexp + nll (rows L2-hot from staging)
    double lsum = 0.0;
    for (int rr = wid; rr < MT; rr += 8) {
        if (tile0 + rr >= cnt) break;             // uniform within warp
        int row = ridx[rr];
        int jbest = jb[rr];
        const float* xr = x + (size_t)row * CDIM;
        float v0 = xr[lane], v1 = xr[lane + 32], v2 = xr[lane + 64], v3 = xr[lane + 96];
        float mx = fmaxf(fmaxf(v0, v1), fmaxf(v2, v3));
        #pragma unroll
        for (int o = 16; o; o >>= 1) mx = fmaxf(mx, __shfl_xor_sync(0xffffffffu, mx, o));
        float s = __expf(v0 - mx) + __expf(v1 - mx) + __expf(v2 - mx) + __expf(v3 - mx);
        #pragma unroll
        for (int o = 16; o; o >>= 1) s += __shfl_xor_sync(0xffffffffu, s, o);
        int slot = jbest >> 5;
        float cand = (slot == 0) ? v0 : (slot == 1) ? v1 : (slot == 2) ? v2 : v3;
        float xl = __shfl_sync(0xffffffffu, cand, jbest & 31);
        if (lane == 0) lsum += (double)((mx + __logf(s)) - xl);
    }
    if (lane == 0 && lsum != 0.0) atomicAdd(&g_acc, lsum);
}

__global__ void k_final(float* out, int N) { out[0] = (float)(g_acc / (double)N); }

extern "C" void kernel_launch(void* const* d_in, const int* in_sizes, int n_in,
                              void* d_out, int out_size)
{
    const float* x      = (const float*)d_in[0];
    const int*   labels = (const int*)d_in[1];
    const float* protos = (const float*)d_in[2];
    const int*   kp     = (n_in > 3) ? (const int*)d_in[3] : nullptr;
    int N = in_sizes[0] / CDIM;

    k_prep<<<1, 256>>>(protos);
    k_labeled<<<592, 256>>>(x, labels, kp, N);
    int nb = (N + MT - 1) / MT;                 // worst case; excess blocks exit on g_cnt
    k_gemm<<<nb, 256>>>(x);
    k_final<<<1, 1>>>((float*)d_out, N);
}

// round 5
// speedup vs baseline: 2.9854x; 1.4137x over previous
#include <cuda_runtime.h>
#include <cuda_bf16.h>
#include <math.h>
#include <stdint.h>

#define CDIM 128
#define KDIM 128
#define MT 128
#define XS 72              // smem row stride in bf16 (64 data + 8 pad)

// ---------------- replay-safe device scratch ----------------
__device__ double g_acc;
__device__ float  g_qv[KDIM];
__device__ unsigned char g_pb[2 * KDIM * 64 * 2];  // protos bf16, [chunk][j][64]

// Prep: reset accumulator, 0.5*||p||^2, protos -> bf16 chunked tiles.
__global__ void k_prep(const float* __restrict__ protos)
{
    int t = threadIdx.x;
    if (t == 0) g_acc = 0.0;
    if (t < KDIM) {
        const float* pr = protos + t * CDIM;
        float s = 0.f;
        #pragma unroll 8
        for (int c = 0; c < CDIM; c++) { float v = pr[c]; s = fmaf(v, v, s); }
        g_qv[t] = 0.5f * s;
    }
    for (int idx = t; idx < 2 * KDIM * 64; idx += blockDim.x) {
        int ch = idx >> 13;
        int j  = (idx >> 6) & 127;
        int kk = idx & 63;
        float v = protos[j * CDIM + ch * 64 + kk];
        ((__nv_bfloat16*)g_pb)[ch * KDIM * 64 + j * 64 + kk] = __float2bfloat16(v);
    }
}

__device__ __forceinline__ void mma16816(float* c4, uint32_t a0, uint32_t a1,
                                         uint32_t a2, uint32_t a3,
                                         uint32_t b0, uint32_t b1) {
    asm volatile("mma.sync.aligned.m16n8k16.row.col.f32.bf16.bf16.f32 "
                 "{%0,%1,%2,%3}, {%4,%5,%6,%7}, {%8,%9}, {%0,%1,%2,%3};"
                 : "+f"(c4[0]), "+f"(c4[1]), "+f"(c4[2]), "+f"(c4[3])
                 : "r"(a0), "r"(a1), "r"(a2), "r"(a3), "r"(b0), "r"(b1));
}

// Single fused pass over ALL rows: stage (x read ONCE, fused exp-sum) ->
// HMMA scores -> argmax -> effective label -> nll -> block-reduced atomic.
__global__ void __launch_bounds__(256, 2)
k_main(const float* __restrict__ x, const int* __restrict__ labels,
       const int* __restrict__ kp, int N)
{
    __shared__ __nv_bfloat16 Xsm[MT * XS];    // 18.4 KB
    __shared__ __nv_bfloat16 Psm[KDIM * XS];  // 18.4 KB
    __shared__ float  qs[KDIM];
    __shared__ float  rowsum[MT];
    __shared__ int    jbs[MT];
    __shared__ double wpart[8];

    int tile0 = blockIdx.x * MT;
    int t = threadIdx.x, wid = t >> 5, lane = t & 31;
    int g = lane >> 2, q = lane & 3;
    int rbase = wid * 16;
    int k = kp ? *kp : 128;

    if (t < MT) qs[t] = g_qv[t];

    float acc[16][4];
    #pragma unroll
    for (int j = 0; j < 16; j++)
        #pragma unroll
        for (int n = 0; n < 4; n++) acc[j][n] = 0.f;
    float pr[8];
    #pragma unroll
    for (int it = 0; it < 8; it++) pr[it] = 0.f;

    for (int ch = 0; ch < 2; ch++) {
        if (ch) __syncthreads();
        // stage X chunk: 128 contiguous rows x 64 c; fp32 -> bf16 + fused exp-sum
        #pragma unroll
        for (int it = 0; it < 8; it++) {
            int idx = t + it * 256;               // 0..2047 float4s
            int row = idx >> 4, c4 = idx & 15;
            int grow = tile0 + row; if (grow >= N) grow = N - 1;
            float4 v = *(const float4*)(x + (size_t)grow * CDIM + ch * 64 + c4 * 4);
            pr[it] += (__expf(v.x) + __expf(v.y)) + (__expf(v.z) + __expf(v.w));
            __nv_bfloat162 h0 = __floats2bfloat162_rn(v.x, v.y);
            __nv_bfloat162 h1 = __floats2bfloat162_rn(v.z, v.w);
            uint2 pk; pk.x = *(uint32_t*)&h0; pk.y = *(uint32_t*)&h1;
            *(uint2*)&Xsm[row * XS + c4 * 4] = pk;
        }
        // stage P chunk: copy preconverted bf16 (tight [j][64] -> padded [j][XS])
        #pragma unroll
        for (int it = 0; it < 4; it++) {
            int idx = t + it * 256;               // 0..1023 uint4s
            int j = idx >> 3, c8 = idx & 7;
            *(uint4*)&Psm[j * XS + c8 * 8] =
                *(const uint4*)((const __nv_bfloat16*)g_pb + ch * KDIM * 64 + j * 64 + c8 * 8);
        }
        __syncthreads();

        #pragma unroll
        for (int kk = 0; kk < 4; kk++) {
            const __nv_bfloat16* Xw = &Xsm[(rbase + g) * XS + kk * 16 + q * 2];
            uint32_t a0 = *(const uint32_t*)&Xw[0];
            uint32_t a1 = *(const uint32_t*)&Xw[8 * XS];
            uint32_t a2 = *(const uint32_t*)&Xw[8];
            uint32_t a3 = *(const uint32_t*)&Xw[8 * XS + 8];
            #pragma unroll
            for (int j0 = 0; j0 < 16; j0++) {
                const __nv_bfloat16* Pw = &Psm[(j0 * 8 + g) * XS + kk * 16 + q * 2];
                uint32_t b0 = *(const uint32_t*)&Pw[0];
                uint32_t b1 = *(const uint32_t*)&Pw[8];
                mma16816(acc[j0], a0, a1, a2, a3, b0, b1);
            }
        }
    }

    // per-row exp-sums: width-16 shfl tree; lane c4==0 writes the row
    #pragma unroll
    for (int it = 0; it < 8; it++) {
        float s = pr[it];
        #pragma unroll
        for (int o = 8; o; o >>= 1) s += __shfl_xor_sync(0xffffffffu, s, o, 16);
        if ((t & 15) == 0) rowsum[(t + it * 256) >> 4] = s;
    }

    // argmax: thread covers rows {rbase+g, rbase+g+8}, cols {j0*8+2q, +1}
    float bv0 = -3.0e38f, bv1 = -3.0e38f;
    int bj0 = 0, bj1 = 0;
    #pragma unroll
    for (int j0 = 0; j0 < 16; j0++) {
        int c0 = j0 * 8 + q * 2;
        float q0 = qs[c0], q1 = qs[c0 + 1];
        float s;
        s = acc[j0][0] - q0; if (s > bv0) { bv0 = s; bj0 = c0; }
        s = acc[j0][1] - q1; if (s > bv0) { bv0 = s; bj0 = c0 + 1; }
        s = acc[j0][2] - q0; if (s > bv1) { bv1 = s; bj1 = c0; }
        s = acc[j0][3] - q1; if (s > bv1) { bv1 = s; bj1 = c0 + 1; }
    }
    #pragma unroll
    for (int o = 1; o < 4; o <<= 1) {       // reduce across q group (width 4)
        float v2 = __shfl_xor_sync(0xffffffffu, bv0, o, 4);
        int   j2 = __shfl_xor_sync(0xffffffffu, bj0, o, 4);
        if (v2 > bv0 || (v2 == bv0 && j2 < bj0)) { bv0 = v2; bj0 = j2; }
        v2 = __shfl_xor_sync(0xffffffffu, bv1, o, 4);
        j2 = __shfl_xor_sync(0xffffffffu, bj1, o, 4);
        if (v2 > bv1 || (v2 == bv1 && j2 < bj1)) { bv1 = v2; bj1 = j2; }
    }
    if (q == 0) { jbs[rbase + g] = bj0; jbs[rbase + g + 8] = bj1; }
    __syncthreads();

    // per-row nll (threads 0..127); x[row][label] is L2-hot from staging
    double nll = 0.0;
    if (t < MT && tile0 + t < N) {
        int grow = tile0 + t;
        int lab = labels[grow];
        int leff = (lab <= k - 1) ? lab : jbs[t];
        float xl = x[(size_t)grow * CDIM + leff];
        nll = (double)(__logf(rowsum[t]) - xl);
    }
    #pragma unroll
    for (int o = 16; o; o >>= 1) nll += __shfl_xor_sync(0xffffffffu, nll, o);
    if (lane == 0) wpart[wid] = nll;
    __syncthreads();
    if (t == 0) {
        double s = wpart[0] + wpart[1] + wpart[2] + wpart[3];
        atomicAdd(&g_acc, s);
    }
}

__global__ void k_final(float* out, int N) { out[0] = (float)(g_acc / (double)N); }

extern "C" void kernel_launch(void* const* d_in, const int* in_sizes, int n_in,
                              void* d_out, int out_size)
{
    const float* x      = (const float*)d_in[0];
    const int*   labels = (const int*)d_in[1];
    const float* protos = (const float*)d_in[2];
    const int*   kp     = (n_in > 3) ? (const int*)d_in[3] : nullptr;
    int N = in_sizes[0] / CDIM;

    k_prep<<<1, 256>>>(protos);
    int nb = (N + MT - 1) / MT;
    k_main<<<nb, 256>>>(x, labels, kp, N);
    k_final<<<1, 1>>>((float*)d_out, N);
}

// round 6
// speedup vs baseline: 2.9944x; 1.0030x over previous
#include <cuda_runtime.h>
#include <cuda_bf16.h>
#include <math.h>
#include <stdint.h>

#define CDIM 128
#define KDIM 128
#define MT 128
#define XS 72              // smem row stride in bf16 (64 data + 8 pad)

// ---------------- replay-safe device scratch ----------------
__device__ double g_acc;
__device__ unsigned int g_done;
__device__ float  g_qv[KDIM];
__device__ unsigned char g_pb[2 * KDIM * 64 * 2];  // protos bf16, [chunk][j][64]

// Prep (wide): reset accumulators, 0.5*||p||^2, protos -> bf16 chunked tiles.
__global__ void k_prep(const float* __restrict__ protos)
{
    int t = threadIdx.x;
    if (blockIdx.x == 0) {
        if (t == 0) { g_acc = 0.0; g_done = 0u; }
        if (t < KDIM) {
            const float* pr = protos + t * CDIM;
            float s = 0.f;
            #pragma unroll 8
            for (int c = 0; c < CDIM; c++) { float v = pr[c]; s = fmaf(v, v, s); }
            g_qv[t] = 0.5f * s;
        }
    }
    int gt = blockIdx.x * blockDim.x + t;
    int stride = gridDim.x * blockDim.x;
    for (int idx = gt; idx < 2 * KDIM * 64; idx += stride) {
        int ch = idx >> 13;
        int j  = (idx >> 6) & 127;
        int kk = idx & 63;
        float v = protos[j * CDIM + ch * 64 + kk];
        ((__nv_bfloat16*)g_pb)[ch * KDIM * 64 + j * 64 + kk] = __float2bfloat16(v);
    }
}

__device__ __forceinline__ void mma16816(float* c4, uint32_t a0, uint32_t a1,
                                         uint32_t a2, uint32_t a3,
                                         uint32_t b0, uint32_t b1) {
    asm volatile("mma.sync.aligned.m16n8k16.row.col.f32.bf16.bf16.f32 "
                 "{%0,%1,%2,%3}, {%4,%5,%6,%7}, {%8,%9}, {%0,%1,%2,%3};"
                 : "+f"(c4[0]), "+f"(c4[1]), "+f"(c4[2]), "+f"(c4[3])
                 : "r"(a0), "r"(a1), "r"(a2), "r"(a3), "r"(b0), "r"(b1));
}

// Single fused pass over ALL rows: stage (x read ONCE, fused exp-sum) ->
// HMMA scores -> argmax -> effective label -> nll -> block atomic;
// last-finishing CTA writes the final mean (fused k_final).
__global__ void __launch_bounds__(256, 2)
k_main(const float* __restrict__ x, const int* __restrict__ labels,
       const int* __restrict__ kp, int N, float* __restrict__ out)
{
    __shared__ __nv_bfloat16 Xsm[MT * XS];    // 18.4 KB
    __shared__ __nv_bfloat16 Psm[KDIM * XS];  // 18.4 KB
    __shared__ float  qs[KDIM];
    __shared__ float  rowsum[MT];
    __shared__ int    jbs[MT];
    __shared__ double wpart[8];

    int tile0 = blockIdx.x * MT;
    int t = threadIdx.x, wid = t >> 5, lane = t & 31;
    int g = lane >> 2, q = lane & 3;
    int rbase = wid * 16;
    int k = kp ? *kp : 128;

    // prefetch per-row label + qv early (hides epilogue LDG latency)
    int myLab = 0;
    if (t < MT) {
        qs[t] = g_qv[t];
        int grow = tile0 + t;
        if (grow < N) myLab = labels[grow];
    }

    float acc[16][4];
    #pragma unroll
    for (int j = 0; j < 16; j++)
        #pragma unroll
        for (int n = 0; n < 4; n++) acc[j][n] = 0.f;
    float pr[8];
    #pragma unroll
    for (int it = 0; it < 8; it++) pr[it] = 0.f;

    for (int ch = 0; ch < 2; ch++) {
        if (ch) __syncthreads();
        // stage X chunk: 128 contiguous rows x 64 c; fp32 -> bf16 + fused exp-sum
        #pragma unroll
        for (int it = 0; it < 8; it++) {
            int idx = t + it * 256;               // 0..2047 float4s
            int row = idx >> 4, c4 = idx & 15;
            int grow = tile0 + row; if (grow >= N) grow = N - 1;
            float4 v = *(const float4*)(x + (size_t)grow * CDIM + ch * 64 + c4 * 4);
            pr[it] += (__expf(v.x) + __expf(v.y)) + (__expf(v.z) + __expf(v.w));
            __nv_bfloat162 h0 = __floats2bfloat162_rn(v.x, v.y);
            __nv_bfloat162 h1 = __floats2bfloat162_rn(v.z, v.w);
            uint2 pk; pk.x = *(uint32_t*)&h0; pk.y = *(uint32_t*)&h1;
            *(uint2*)&Xsm[row * XS + c4 * 4] = pk;
        }
        // stage P chunk: copy preconverted bf16 (tight [j][64] -> padded [j][XS])
        #pragma unroll
        for (int it = 0; it < 4; it++) {
            int idx = t + it * 256;               // 0..1023 uint4s
            int j = idx >> 3, c8 = idx & 7;
            *(uint4*)&Psm[j * XS + c8 * 8] =
                *(const uint4*)((const __nv_bfloat16*)g_pb + ch * KDIM * 64 + j * 64 + c8 * 8);
        }
        __syncthreads();

        #pragma unroll
        for (int kk = 0; kk < 4; kk++) {
            const __nv_bfloat16* Xw = &Xsm[(rbase + g) * XS + kk * 16 + q * 2];
            uint32_t a0 = *(const uint32_t*)&Xw[0];
            uint32_t a1 = *(const uint32_t*)&Xw[8 * XS];
            uint32_t a2 = *(const uint32_t*)&Xw[8];
            uint32_t a3 = *(const uint32_t*)&Xw[8 * XS + 8];
            #pragma unroll
            for (int j0 = 0; j0 < 16; j0++) {
                const __nv_bfloat16* Pw = &Psm[(j0 * 8 + g) * XS + kk * 16 + q * 2];
                uint32_t b0 = *(const uint32_t*)&Pw[0];
                uint32_t b1 = *(const uint32_t*)&Pw[8];
                mma16816(acc[j0], a0, a1, a2, a3, b0, b1);
            }
        }
    }

    // per-row exp-sums: width-16 shfl tree; lane c4==0 writes the row
    #pragma unroll
    for (int it = 0; it < 8; it++) {
        float s = pr[it];
        #pragma unroll
        for (int o = 8; o; o >>= 1) s += __shfl_xor_sync(0xffffffffu, s, o, 16);
        if ((t & 15) == 0) rowsum[(t + it * 256) >> 4] = s;
    }

    // argmax: thread covers rows {rbase+g, rbase+g+8}, cols {j0*8+2q, +1}
    float bv0 = -3.0e38f, bv1 = -3.0e38f;
    int bj0 = 0, bj1 = 0;
    #pragma unroll
    for (int j0 = 0; j0 < 16; j0++) {
        int c0 = j0 * 8 + q * 2;
        float q0 = qs[c0], q1 = qs[c0 + 1];
        float s;
        s = acc[j0][0] - q0; if (s > bv0) { bv0 = s; bj0 = c0; }
        s = acc[j0][1] - q1; if (s > bv0) { bv0 = s; bj0 = c0 + 1; }
        s = acc[j0][2] - q0; if (s > bv1) { bv1 = s; bj1 = c0; }
        s = acc[j0][3] - q1; if (s > bv1) { bv1 = s; bj1 = c0 + 1; }
    }
    #pragma unroll
    for (int o = 1; o < 4; o <<= 1) {       // reduce across q group (width 4)
        float v2 = __shfl_xor_sync(0xffffffffu, bv0, o, 4);
        int   j2 = __shfl_xor_sync(0xffffffffu, bj0, o, 4);
        if (v2 > bv0 || (v2 == bv0 && j2 < bj0)) { bv0 = v2; bj0 = j2; }
        v2 = __shfl_xor_sync(0xffffffffu, bv1, o, 4);
        j2 = __shfl_xor_sync(0xffffffffu, bj1, o, 4);
        if (v2 > bv1 || (v2 == bv1 && j2 < bj1)) { bv1 = v2; bj1 = j2; }
    }
    if (q == 0) { jbs[rbase + g] = bj0; jbs[rbase + g + 8] = bj1; }
    __syncthreads();

    // per-row nll (threads 0..127); x[row][label] is L2-hot from staging
    double nll = 0.0;
    if (t < MT && tile0 + t < N) {
        int grow = tile0 + t;
        int leff = (myLab <= k - 1) ? myLab : jbs[t];
        float xl = x[(size_t)grow * CDIM + leff];
        nll = (double)(__logf(rowsum[t]) - xl);
    }
    #pragma unroll
    for (int o = 16; o; o >>= 1) nll += __shfl_xor_sync(0xffffffffu, nll, o);
    if (lane == 0) wpart[wid] = nll;
    __syncthreads();
    if (t == 0) {
        double s = wpart[0] + wpart[1] + wpart[2] + wpart[3];
        atomicAdd(&g_acc, s);
        __threadfence();
        unsigned int done = atomicAdd(&g_done, 1u);
        if (done == gridDim.x - 1) {            // last CTA: fused finalization
            out[0] = (float)(g_acc / (double)N);
        }
    }
}

extern "C" void kernel_launch(void* const* d_in, const int* in_sizes, int n_in,
                              void* d_out, int out_size)
{
    const float* x      = (const float*)d_in[0];
    const int*   labels = (const int*)d_in[1];
    const float* protos = (const float*)d_in[2];
    const int*   kp     = (n_in > 3) ? (const int*)d_in[3] : nullptr;
    int N = in_sizes[0] / CDIM;

    k_prep<<<148, 256>>>(protos);
    int nb = (N + MT - 1) / MT;
    k_main<<<nb, 256>>>(x, labels, kp, N, (float*)d_out);
}

// round 7
// speedup vs baseline: 4.6310x; 1.5465x over previous
#include <cuda_runtime.h>
#include <cuda_bf16.h>
#include <math.h>
#include <stdint.h>

#define CDIM 128
#define KDIM 128
#define MT 128
#define XS 72              // Psm row stride (bf16)
#define XF 68              // X fp32 smem row stride (floats)
#define GRID 296

__device__ double g_acc;
__device__ unsigned int g_done;
__device__ float  g_qv[KDIM];
__device__ unsigned char g_pb[2 * KDIM * 64 * 2];  // protos bf16 [chunk][j][64]

__device__ __forceinline__ uint32_t smem_u32(const void* p) {
    uint32_t a;
    asm("{ .reg .u64 t; cvta.to.shared.u64 t, %1; cvt.u32.u64 %0, t; }" : "=r"(a) : "l"(p));
    return a;
}
__device__ __forceinline__ void cpa16(void* dst, const void* src) {
    asm volatile("cp.async.cg.shared.global [%0], [%1], 16;"
                 :: "r"(smem_u32(dst)), "l"(src));
}
#define CPA_COMMIT() asm volatile("cp.async.commit_group;" ::: "memory")
#define CPA_WAIT1()  asm volatile("cp.async.wait_group 1;" ::: "memory")

__global__ void k_prep(const float* __restrict__ protos)
{
    int t = threadIdx.x;
    if (blockIdx.x == 0) {
        if (t == 0) { g_acc = 0.0; g_done = 0u; }
        if (t < KDIM) {
            const float* pr = protos + t * CDIM;
            float s = 0.f;
            #pragma unroll 8
            for (int c = 0; c < CDIM; c++) { float v = pr[c]; s = fmaf(v, v, s); }
            g_qv[t] = 0.5f * s;
        }
    }
    int gt = blockIdx.x * blockDim.x + t;
    int stride = gridDim.x * blockDim.x;
    for (int idx = gt; idx < 2 * KDIM * 64; idx += stride) {
        int ch = idx >> 13, j = (idx >> 6) & 127, kk = idx & 63;
        ((__nv_bfloat16*)g_pb)[ch * KDIM * 64 + j * 64 + kk] =
            __float2bfloat16(protos[j * CDIM + ch * 64 + kk]);
    }
}

__device__ __forceinline__ void mma16816(float* c4, uint32_t a0, uint32_t a1,
                                         uint32_t a2, uint32_t a3,
                                         uint32_t b0, uint32_t b1) {
    asm volatile("mma.sync.aligned.m16n8k16.row.col.f32.bf16.bf16.f32 "
                 "{%0,%1,%2,%3}, {%4,%5,%6,%7}, {%8,%9}, {%0,%1,%2,%3};"
                 : "+f"(c4[0]), "+f"(c4[1]), "+f"(c4[2]), "+f"(c4[3])
                 : "r"(a0), "r"(a1), "r"(a2), "r"(a3), "r"(b0), "r"(b1));
}
__device__ __forceinline__ uint32_t pkbf(float a, float b) {
    __nv_bfloat162 h = __floats2bfloat162_rn(a, b);
    return *(uint32_t*)&h;
}

// Persistent pipelined pass: cp.async X chunks (fp32) double-buffered,
// P resident in smem; exp-sum + bf16 convert fused into A-fragment loads.
__global__ void __launch_bounds__(256, 2)
k_main(const float* __restrict__ x, const int* __restrict__ labels,
       const int* __restrict__ kp, int N, float* __restrict__ out)
{
    extern __shared__ char dsm[];
    __nv_bfloat16* Psm = (__nv_bfloat16*)dsm;                 // [2][128][XS] 36864B
    float* Xb   = (float*)(dsm + 36864);                      // [2][128][XF] 69632B
    float* qs   = (float*)(dsm + 36864 + 69632);              // 128
    float* rowsum = qs + 128;                                 // 128
    int*   jbs  = (int*)(rowsum + 128);                       // 128
    double* wpart = (double*)(jbs + 128);                     // 8

    int nt = (N + MT - 1) / MT;
    int t = threadIdx.x, wid = t >> 5, lane = t & 31;
    int g = lane >> 2, q = lane & 3;
    int rbase = wid * 16;
    int k = kp ? *kp : 128;

    // ---- prime: group0 = P + qs-independent X(tile0,ch0); group1 = X(tile0,ch1)
    int tile = blockIdx.x;
    if (t < 128) qs[t] = g_qv[t];
    #pragma unroll
    for (int it = 0; it < 8; it++) {               // P: 2048 x 16B
        int idx = t + it * 256;
        int ch = idx >> 10, rem = idx & 1023;
        int j = rem >> 3, seg = rem & 7;
        cpa16((char*)Psm + (ch * 128 + j) * (XS * 2) + seg * 16,
              g_pb + ch * 16384 + j * 128 + seg * 16);
    }
    {
        size_t base = (size_t)tile * MT * CDIM;
        #pragma unroll
        for (int it = 0; it < 8; it++) {           // X(tile, ch0)
            int idx = t + it * 256;
            int row = idx >> 4, seg = idx & 15;
            cpa16(Xb + row * XF + seg * 4, x + base + row * CDIM + seg * 4);
        }
        CPA_COMMIT();
        #pragma unroll
        for (int it = 0; it < 8; it++) {           // X(tile, ch1)
            int idx = t + it * 256;
            int row = idx >> 4, seg = idx & 15;
            cpa16(Xb + 128 * XF + row * XF + seg * 4,
                  x + base + row * CDIM + 64 + seg * 4);
        }
        CPA_COMMIT();
    }

    double nll_acc = 0.0;

    for (; tile < nt; tile += GRID) {
        int tile0 = tile * MT;
        float acc[16][4];
        #pragma unroll
        for (int j = 0; j < 16; j++)
            #pragma unroll
            for (int n = 0; n < 4; n++) acc[j][n] = 0.f;
        float rs0 = 0.f, rs1 = 0.f;
        int myLab = 0;

        #pragma unroll
        for (int ch = 0; ch < 2; ch++) {
            CPA_WAIT1();
            __syncthreads();
            if (ch == 0 && t < MT) myLab = labels[tile0 + t];  // hidden by MMA

            const float* Xc = Xb + ch * (128 * XF);
            const __nv_bfloat16* Pc = Psm + ch * (128 * XS);
            #pragma unroll
            for (int kk = 0; kk < 4; kk++) {
                int ab = (rbase + g) * XF + kk * 16 + q * 2;
                float2 v00 = *(const float2*)&Xc[ab];
                float2 v01 = *(const float2*)&Xc[ab + 8];
                float2 v10 = *(const float2*)&Xc[ab + 8 * XF];
                float2 v11 = *(const float2*)&Xc[ab + 8 * XF + 8];
                rs0 += (__expf(v00.x) + __expf(v00.y)) + (__expf(v01.x) + __expf(v01.y));
                rs1 += (__expf(v10.x) + __expf(v10.y)) + (__expf(v11.x) + __expf(v11.y));
                uint32_t a0 = pkbf(v00.x, v00.y), a2 = pkbf(v01.x, v01.y);
                uint32_t a1 = pkbf(v10.x, v10.y), a3 = pkbf(v11.x, v11.y);
                #pragma unroll
                for (int j0 = 0; j0 < 16; j0++) {
                    const __nv_bfloat16* Pw = &Pc[(j0 * 8 + g) * XS + kk * 16 + q * 2];
                    uint32_t b0 = *(const uint32_t*)&Pw[0];
                    uint32_t b1 = *(const uint32_t*)&Pw[8];
                    mma16816(acc[j0], a0, a1, a2, a3, b0, b1);
                }
            }
            if (ch == 1) {                          // finalize rowsums (width-4)
                #pragma unroll
                for (int o = 1; o < 4; o <<= 1) {
                    rs0 += __shfl_xor_sync(0xffffffffu, rs0, o, 4);
                    rs1 += __shfl_xor_sync(0xffffffffu, rs1, o, 4);
                }
                if (q == 0) { rowsum[rbase + g] = rs0; rowsum[rbase + g + 8] = rs1; }
            }
            __syncthreads();
            // prefetch same chunk of tile+GRID into this buffer
            int ntile = tile + GRID;
            if (ntile < nt) {
                size_t base = (size_t)ntile * MT * CDIM + ch * 64;
                float* dstb = Xb + ch * (128 * XF);
                #pragma unroll
                for (int it = 0; it < 8; it++) {
                    int idx = t + it * 256;
                    int row = idx >> 4, seg = idx & 15;
                    cpa16(dstb + row * XF + seg * 4, x + base + row * CDIM + seg * 4);
                }
            }
            CPA_COMMIT();
        }

        // ---- epilogue: argmax -> effective label -> nll
        float bv0 = -3.0e38f, bv1 = -3.0e38f;
        int bj0 = 0, bj1 = 0;
        #pragma unroll
        for (int j0 = 0; j0 < 16; j0++) {
            int c0 = j0 * 8 + q * 2;
            float q0 = qs[c0], q1 = qs[c0 + 1];
            float s;
            s = acc[j0][0] - q0; if (s > bv0) { bv0 = s; bj0 = c0; }
            s = acc[j0][1] - q1; if (s > bv0) { bv0 = s; bj0 = c0 + 1; }
            s = acc[j0][2] - q0; if (s > bv1) { bv1 = s; bj1 = c0; }
            s = acc[j0][3] - q1; if (s > bv1) { bv1 = s; bj1 = c0 + 1; }
        }
        #pragma unroll
        for (int o = 1; o < 4; o <<= 1) {
            float v2 = __shfl_xor_sync(0xffffffffu, bv0, o, 4);
            int   j2 = __shfl_xor_sync(0xffffffffu, bj0, o, 4);
            if (v2 > bv0 || (v2 == bv0 && j2 < bj0)) { bv0 = v2; bj0 = j2; }
            v2 = __shfl_xor_sync(0xffffffffu, bv1, o, 4);
            j2 = __shfl_xor_sync(0xffffffffu, bj1, o, 4);
            if (v2 > bv1 || (v2 == bv1 && j2 < bj1)) { bv1 = v2; bj1 = j2; }
        }
        if (q == 0) { jbs[rbase + g] = bj0; jbs[rbase + g + 8] = bj1; }
        __syncthreads();

        if (t < MT && tile0 + t < N) {
            int leff = (myLab <= k - 1) ? myLab : jbs[t];
            float xl = x[(size_t)(tile0 + t) * CDIM + leff];   // L2-hot (.cg)
            nll_acc += (double)(__logf(rowsum[t]) - xl);
        }
        __syncthreads();   // jbs/rowsum reuse safety for next tile
    }

    // ---- final block reduction + fused finalization
    #pragma unroll
    for (int o = 16; o; o >>= 1) nll_acc += __shfl_xor_sync(0xffffffffu, nll_acc, o);
    if (lane == 0) wpart[wid] = nll_acc;
    __syncthreads();
    if (t == 0) {
        double s = 0.0;
        #pragma unroll
        for (int i = 0; i < 8; i++) s += wpart[i];
        atomicAdd(&g_acc, s);
        __threadfence();
        unsigned int done = atomicAdd(&g_done, 1u);
        if (done == gridDim.x - 1) out[0] = (float)(g_acc / (double)N);
    }
}

extern "C" void kernel_launch(void* const* d_in, const int* in_sizes, int n_in,
                              void* d_out, int out_size)
{
    const float* x      = (const float*)d_in[0];
    const int*   labels = (const int*)d_in[1];
    const float* protos = (const float*)d_in[2];
    const int*   kp     = (n_in > 3) ? (const int*)d_in[3] : nullptr;
    int N = in_sizes[0] / CDIM;

    static const int SMEM = 36864 + 69632 + 512 + 512 + 512 + 64;
    cudaFuncSetAttribute(k_main, cudaFuncAttributeMaxDynamicSharedMemorySize, SMEM);

    k_prep<<<148, 256>>>(protos);
    k_main<<<GRID, 256, SMEM>>>(x, labels, kp, N, (float*)d_out);
}

// round 8
// speedup vs baseline: 4.7929x; 1.0350x over previous
#include <cuda_runtime.h>
#include <cuda_bf16.h>
#include <math.h>
#include <stdint.h>

#define CDIM 128
#define KDIM 128
#define MT 128
#define XS 72              // Psm row stride (bf16)
#define XF 68              // X fp32 smem row stride (floats)
#define GRID 296

__device__ double g_acc;
__device__ unsigned int g_done;
__device__ float  g_qv[KDIM];
__device__ unsigned char g_pb[2 * KDIM * 64 * 2];  // protos bf16 [chunk][j][64]

__device__ __forceinline__ uint32_t smem_u32(const void* p) {
    uint32_t a;
    asm("{ .reg .u64 t; cvta.to.shared.u64 t, %1; cvt.u32.u64 %0, t; }" : "=r"(a) : "l"(p));
    return a;
}
__device__ __forceinline__ void cpa16(void* dst, const void* src) {
    asm volatile("cp.async.cg.shared.global [%0], [%1], 16;"
                 :: "r"(smem_u32(dst)), "l"(src));
}
#define CPA_COMMIT() asm volatile("cp.async.commit_group;" ::: "memory")
#define CPA_WAIT1()  asm volatile("cp.async.wait_group 1;" ::: "memory")

__device__ __forceinline__ void ldsm4(uint32_t& r0, uint32_t& r1, uint32_t& r2,
                                      uint32_t& r3, uint32_t addr) {
    asm volatile("ldmatrix.sync.aligned.m8n8.x4.shared.b16 {%0,%1,%2,%3}, [%4];"
                 : "=r"(r0), "=r"(r1), "=r"(r2), "=r"(r3) : "r"(addr));
}

__global__ void k_prep(const float* __restrict__ protos)
{
    int t = threadIdx.x;
    if (blockIdx.x == 0) {
        if (t == 0) { g_acc = 0.0; g_done = 0u; }
        if (t < KDIM) {
            const float* pr = protos + t * CDIM;
            float s = 0.f;
            #pragma unroll 8
            for (int c = 0; c < CDIM; c++) { float v = pr[c]; s = fmaf(v, v, s); }
            g_qv[t] = 0.5f * s;
        }
    }
    int gt = blockIdx.x * blockDim.x + t;
    int stride = gridDim.x * blockDim.x;
    for (int idx = gt; idx < 2 * KDIM * 64; idx += stride) {
        int ch = idx >> 13, j = (idx >> 6) & 127, kk = idx & 63;
        ((__nv_bfloat16*)g_pb)[ch * KDIM * 64 + j * 64 + kk] =
            __float2bfloat16(protos[j * CDIM + ch * 64 + kk]);
    }
}

__device__ __forceinline__ void mma16816(float* c4, uint32_t a0, uint32_t a1,
                                         uint32_t a2, uint32_t a3,
                                         uint32_t b0, uint32_t b1) {
    asm volatile("mma.sync.aligned.m16n8k16.row.col.f32.bf16.bf16.f32 "
                 "{%0,%1,%2,%3}, {%4,%5,%6,%7}, {%8,%9}, {%0,%1,%2,%3};"
                 : "+f"(c4[0]), "+f"(c4[1]), "+f"(c4[2]), "+f"(c4[3])
                 : "r"(a0), "r"(a1), "r"(a2), "r"(a3), "r"(b0), "r"(b1));
}
__device__ __forceinline__ uint32_t pkbf(float a, float b) {
    __nv_bfloat162 h = __floats2bfloat162_rn(a, b);
    return *(uint32_t*)&h;
}

// Persistent pipelined pass: cp.async X chunks (fp32) double-buffered,
// P resident in smem and fetched via ldmatrix.x4; exp-sum + bf16 convert
// fused into A-fragment loads.
__global__ void __launch_bounds__(256, 2)
k_main(const float* __restrict__ x, const int* __restrict__ labels,
       const int* __restrict__ kp, int N, float* __restrict__ out)
{
    extern __shared__ char dsm[];
    __nv_bfloat16* Psm = (__nv_bfloat16*)dsm;                 // [2][128][XS] 36864B
    float* Xb   = (float*)(dsm + 36864);                      // [2][128][XF] 69632B
    float* qs   = (float*)(dsm + 36864 + 69632);              // 128
    float* rowsum = qs + 128;                                 // 128
    int*   jbs  = (int*)(rowsum + 128);                       // 128
    double* wpart = (double*)(jbs + 128);                     // 8

    int nt = (N + MT - 1) / MT;
    int t = threadIdx.x, wid = t >> 5, lane = t & 31;
    int g = lane >> 2, q = lane & 3;
    int rbase = wid * 16;
    int k = kp ? *kp : 128;

    // per-lane ldmatrix base address (ch=0, kk=0, j0-pair=0):
    // group gsel = lane>>3 selects {b0(j0),b1(j0),b0(j0+1),b1(j0+1)}
    uint32_t lm_base;
    {
        int gsel = lane >> 3, r = lane & 7;
        int row = (gsel >> 1) * 8 + r;              // n-row within pair
        lm_base = smem_u32(Psm) + (uint32_t)(row * XS + (gsel & 1) * 8) * 2u;
    }

    // ---- prime: P + X(tile0, ch0) ; then X(tile0, ch1)
    int tile = blockIdx.x;
    if (t < 128) qs[t] = g_qv[t];
    #pragma unroll
    for (int it = 0; it < 8; it++) {               // P: 2048 x 16B
        int idx = t + it * 256;
        int ch = idx >> 10, rem = idx & 1023;
        int j = rem >> 3, seg = rem & 7;
        cpa16((char*)Psm + (ch * 128 + j) * (XS * 2) + seg * 16,
              g_pb + ch * 16384 + j * 128 + seg * 16);
    }
    {
        size_t base = (size_t)tile * MT * CDIM;
        #pragma unroll
        for (int it = 0; it < 8; it++) {           // X(tile, ch0)
            int idx = t + it * 256;
            int row = idx >> 4, seg = idx & 15;
            cpa16(Xb + row * XF + seg * 4, x + base + row * CDIM + seg * 4);
        }
        CPA_COMMIT();
        #pragma unroll
        for (int it = 0; it < 8; it++) {           // X(tile, ch1)
            int idx = t + it * 256;
            int row = idx >> 4, seg = idx & 15;
            cpa16(Xb + 128 * XF + row * XF + seg * 4,
                  x + base + row * CDIM + 64 + seg * 4);
        }
        CPA_COMMIT();
    }

    double nll_acc = 0.0;

    for (; tile < nt; tile += GRID) {
        int tile0 = tile * MT;
        float acc[16][4];
        #pragma unroll
        for (int j = 0; j < 16; j++)
            #pragma unroll
            for (int n = 0; n < 4; n++) acc[j][n] = 0.f;
        float rs0 = 0.f, rs1 = 0.f;
        int myLab = 0;

        #pragma unroll
        for (int ch = 0; ch < 2; ch++) {
            CPA_WAIT1();
            __syncthreads();
            if (ch == 0 && t < MT) myLab = labels[tile0 + t];  // hidden by MMA

            const float* Xc = Xb + ch * (128 * XF);
            uint32_t lmc = lm_base + (uint32_t)(ch * 128 * XS * 2);
            #pragma unroll
            for (int kk = 0; kk < 4; kk++) {
                int ab = (rbase + g) * XF + kk * 16 + q * 2;
                float2 v00 = *(const float2*)&Xc[ab];
                float2 v01 = *(const float2*)&Xc[ab + 8];
                float2 v10 = *(const float2*)&Xc[ab + 8 * XF];
                float2 v11 = *(const float2*)&Xc[ab + 8 * XF + 8];
                rs0 += (__expf(v00.x) + __expf(v00.y)) + (__expf(v01.x) + __expf(v01.y));
                rs1 += (__expf(v10.x) + __expf(v10.y)) + (__expf(v11.x) + __expf(v11.y));
                uint32_t a0 = pkbf(v00.x, v00.y), a2 = pkbf(v01.x, v01.y);
                uint32_t a1 = pkbf(v10.x, v10.y), a3 = pkbf(v11.x, v11.y);
                uint32_t lmk = lmc + (uint32_t)(kk * 32);
                #pragma unroll
                for (int i = 0; i < 8; i++) {      // j0 pair {2i, 2i+1}
                    uint32_t b0a, b1a, b0b, b1b;
                    ldsm4(b0a, b1a, b0b, b1b, lmk + (uint32_t)(i * 16 * XS * 2));
                    mma16816(acc[2 * i],     a0, a1, a2, a3, b0a, b1a);
                    mma16816(acc[2 * i + 1], a0, a1, a2, a3, b0b, b1b);
                }
            }
            if (ch == 1) {                          // finalize rowsums (width-4)
                #pragma unroll
                for (int o = 1; o < 4; o <<= 1) {
                    rs0 += __shfl_xor_sync(0xffffffffu, rs0, o, 4);
                    rs1 += __shfl_xor_sync(0xffffffffu, rs1, o, 4);
                }
                if (q == 0) { rowsum[rbase + g] = rs0; rowsum[rbase + g + 8] = rs1; }
            }
            __syncthreads();
            // prefetch same chunk of tile+GRID into this buffer
            int ntile = tile + GRID;
            if (ntile < nt) {
                size_t base = (size_t)ntile * MT * CDIM + ch * 64;
                float* dstb = Xb + ch * (128 * XF);
                #pragma unroll
                for (int it = 0; it < 8; it++) {
                    int idx = t + it * 256;
                    int row = idx >> 4, seg = idx & 15;
                    cpa16(dstb + row * XF + seg * 4, x + base + row * CDIM + seg * 4);
                }
            }
            CPA_COMMIT();
        }

        // ---- epilogue: argmax -> effective label -> nll
        float bv0 = -3.0e38f, bv1 = -3.0e38f;
        int bj0 = 0, bj1 = 0;
        #pragma unroll
        for (int j0 = 0; j0 < 16; j0++) {
            int c0 = j0 * 8 + q * 2;
            float q0 = qs[c0], q1 = qs[c0 + 1];
            float s;
            s = acc[j0][0] - q0; if (s > bv0) { bv0 = s; bj0 = c0; }
            s = acc[j0][1] - q1; if (s > bv0) { bv0 = s; bj0 = c0 + 1; }
            s = acc[j0][2] - q0; if (s > bv1) { bv1 = s; bj1 = c0; }
            s = acc[j0][3] - q1; if (s > bv1) { bv1 = s; bj1 = c0 + 1; }
        }
        #pragma unroll
        for (int o = 1; o < 4; o <<= 1) {
            float v2 = __shfl_xor_sync(0xffffffffu, bv0, o, 4);
            int   j2 = __shfl_xor_sync(0xffffffffu, bj0, o, 4);
            if (v2 > bv0 || (v2 == bv0 && j2 < bj0)) { bv0 = v2; bj0 = j2; }
            v2 = __shfl_xor_sync(0xffffffffu, bv1, o, 4);
            j2 = __shfl_xor_sync(0xffffffffu, bj1, o, 4);
            if (v2 > bv1 || (v2 == bv1 && j2 < bj1)) { bv1 = v2; bj1 = j2; }
        }
        if (q == 0) { jbs[rbase + g] = bj0; jbs[rbase + g + 8] = bj1; }
        __syncthreads();

        if (t < MT && tile0 + t < N) {
            int leff = (myLab <= k - 1) ? myLab : jbs[t];
            float xl = x[(size_t)(tile0 + t) * CDIM + leff];   // L2-hot
            nll_acc += (double)(__logf(rowsum[t]) - xl);
        }
        // no extra barrier: next writes to jbs/rowsum are >=2 barriers away
    }

    // ---- final block reduction + fused finalization
    #pragma unroll
    for (int o = 16; o; o >>= 1) nll_acc += __shfl_xor_sync(0xffffffffu, nll_acc, o);
    if (lane == 0) wpart[wid] = nll_acc;
    __syncthreads();
    if (t == 0) {
        double s = 0.0;
        #pragma unroll
        for (int i = 0; i < 8; i++) s += wpart[i];
        atomicAdd(&g_acc, s);
        __threadfence();
        unsigned int done = atomicAdd(&g_done, 1u);
        if (done == gridDim.x - 1) out[0] = (float)(g_acc / (double)N);
    }
}

extern "C" void kernel_launch(void* const* d_in, const int* in_sizes, int n_in,
                              void* d_out, int out_size)
{
    const float* x      = (const float*)d_in[0];
    const int*   labels = (const int*)d_in[1];
    const float* protos = (const float*)d_in[2];
    const int*   kp     = (n_in > 3) ? (const int*)d_in[3] : nullptr;
    int N = in_sizes[0] / CDIM;

    static const int SMEM = 36864 + 69632 + 512 + 512 + 512 + 64;
    cudaFuncSetAttribute(k_main, cudaFuncAttributeMaxDynamicSharedMemorySize, SMEM);

    k_prep<<<148, 256>>>(protos);
    k_main<<<GRID, 256, SMEM>>>(x, labels, kp, N, (float*)d_out);
}